// round 8
// baseline (speedup 1.0000x reference)
#include <cuda_runtime.h>
#include <cstdint>

// LengthRegulator: expand hidden_phonems [B,L,D] by durations [B,L] into
// out [B, max_T, D], zero-padded beyond totals[b].
//
// R8: two kernels, both efficient.
//  K1 (ONE block, 1024 thr): warp w scans batch w's 512 durations
//     (4 int4 loads/lane, local prefix-16, warp-exclusive scan of partials,
//     4 int4 stores) -> full starts table + totals. ~1us.
//  K2 (lean): no reduction, no shuffles, no smem. Warp-uniform scalar loads
//     of start/d/total; exact-trip coalesced STG.128 replication; strided
//     tail zeroing. Low regs -> high occupancy (R7's 512-int per-warp
//     reduction cost 43 regs / 49% occ / 64MB of redundant idx reads).

#define B_CONST 32
#define L_CONST 512
#define D_CONST 256
#define D4 (D_CONST / 4)
#define MAX_DUR 8
#define P_PER_BLK 4
#define BLOCKS_PER_BATCH (L_CONST / P_PER_BLK)   // 128

__device__ int g_starts[B_CONST * L_CONST];
__device__ int g_totals[B_CONST];

// K1: one block, 32 warps; warp w = batch w. Lane handles 16 durations.
__global__ void __launch_bounds__(1024) lr_scan(const int* __restrict__ durations) {
    const int w    = threadIdx.x >> 5;           // batch
    const int lane = threadIdx.x & 31;
    const int base = w * L_CONST + lane * 16;

    // load 16 durations (4 x int4, MLP=4)
    int4 a = *(const int4*)(durations + base);
    int4 b = *(const int4*)(durations + base + 4);
    int4 c = *(const int4*)(durations + base + 8);
    int4 d = *(const int4*)(durations + base + 12);

    int v[16] = { a.x,a.y,a.z,a.w, b.x,b.y,b.z,b.w,
                  c.x,c.y,c.z,c.w, d.x,d.y,d.z,d.w };

    // local inclusive prefix over the 16
    int p[16];
    int run = 0;
    #pragma unroll
    for (int j = 0; j < 16; ++j) { p[j] = run; run += v[j]; }   // p = exclusive

    // warp exclusive scan of the 16-sums
    int s = run;
    #pragma unroll
    for (int o = 1; o < 32; o <<= 1) {
        int n = __shfl_up_sync(0xffffffffu, s, o);
        if (lane >= o) s += n;
    }
    const int excl = s - run;                    // exclusive prefix at lane*16

    // write starts (exclusive prefix at each l)
    int4 o0 = make_int4(excl+p[0],  excl+p[1],  excl+p[2],  excl+p[3]);
    int4 o1 = make_int4(excl+p[4],  excl+p[5],  excl+p[6],  excl+p[7]);
    int4 o2 = make_int4(excl+p[8],  excl+p[9],  excl+p[10], excl+p[11]);
    int4 o3 = make_int4(excl+p[12], excl+p[13], excl+p[14], excl+p[15]);
    *(int4*)(g_starts + base)      = o0;
    *(int4*)(g_starts + base + 4)  = o1;
    *(int4*)(g_starts + base + 8)  = o2;
    *(int4*)(g_starts + base + 12) = o3;

    if (lane == 31) g_totals[w] = s;             // inclusive total of batch
}

// K2: 256 thr/block = 4 phonemes, 64 float4 lanes each.
__global__ void __launch_bounds__(256) lr_expand(
    const float4* __restrict__ hidden4,
    const int*    __restrict__ durations,
    float4*       __restrict__ out4,
    int max_T)
{
    const int t        = threadIdx.x;
    const int blk      = blockIdx.x;
    const int b        = blk >> 7;
    const int blkLocal = blk & (BLOCKS_PER_BATCH - 1);
    const int fgrp     = t >> 6;
    const int lane64   = t & 63;
    const int lp       = blkLocal * P_PER_BLK + fgrp;
    const int gl       = b * L_CONST + lp;

    // row load first (latency hides under the scalar loads below)
    const float4 v = hidden4[(size_t)gl * D4 + lane64];

    const int start = g_starts[gl];              // warp-uniform
    const int d     = durations[gl];             // warp-uniform
    const int total = g_totals[b];               // warp-uniform

    float4* dst = out4 + ((size_t)b * max_T + start) * D4 + lane64;
    for (int j = 0; j < d; ++j)                  // exact trip, warp-uniform
        dst[j * D4] = v;

    // tail zeroing: strided share of [total, max_T)
    const float4 zero = make_float4(0.f, 0.f, 0.f, 0.f);
    for (int f = total + blkLocal * 4 + fgrp; f < max_T; f += 4 * BLOCKS_PER_BATCH) {
        out4[((size_t)b * max_T + f) * D4 + lane64] = zero;
    }
}

extern "C" void kernel_launch(void* const* d_in, const int* in_sizes, int n_in,
                              void* d_out, int out_size) {
    const float* hidden    = (const float*)d_in[0];   // [B, L, D] fp32
    const int*   durations = (const int*)d_in[1];     // [B, L] int32
    float*       out       = (float*)d_out;

    const int max_T = out_size / (B_CONST * D_CONST);

    lr_scan<<<1, 1024>>>(durations);
    lr_expand<<<B_CONST * BLOCKS_PER_BATCH, 256>>>(
        (const float4*)hidden, durations, (float4*)out, max_T);
}

// round 9
// speedup vs baseline: 1.1231x; 1.1231x over previous
#include <cuda_runtime.h>
#include <cstdint>

// LengthRegulator: expand hidden_phonems [B,L,D] by durations [B,L] into
// out [B, max_T, D], zero-padded beyond totals[b].
//
// R9: ONE kernel (every extra launch costs 1.5-3.5us), 16 phonemes per block
// (4x fewer blocks than R7) so the per-warp (total,prefix) reduction is
// amortized over 4x more stores. Software-pipelined row loads; exact-trip
// warp-uniform STG.128 replication; strided tail zeroing.

#define B_CONST 32
#define L_CONST 512
#define D_CONST 256
#define D4 (D_CONST / 4)
#define MAX_DUR 8
#define P_PER_BLK 16
#define BLOCKS_PER_BATCH (L_CONST / P_PER_BLK)   // 32

__global__ void __launch_bounds__(256) lr_fused(
    const float4* __restrict__ hidden4,
    const int*    __restrict__ durations,
    float4*       __restrict__ out4,
    int max_T)
{
    const int t        = threadIdx.x;            // 0..255
    const int blk      = blockIdx.x;             // 0..1023
    const int b        = blk >> 5;               // batch
    const int blkLocal = blk & (BLOCKS_PER_BATCH - 1);
    const int l0       = blkLocal * P_PER_BLK;   // multiple of 16
    const int fgrp     = t >> 6;                 // [0,4): phoneme lane-group
    const int lane64   = t & 63;                 // float4 lane over D
    const int lane     = t & 31;

    const int* __restrict__ dbat = durations + b * L_CONST;

    // ---- per-warp packed reduction over all 512 durations:
    //      low 16 = batch total, high 16 = exclusive prefix(l0).
    //      l0 and quad starts are both multiples of 4 -> no straddle case.
    int packed = 0;
    #pragma unroll
    for (int q = 0; q < 4; ++q) {
        const int i = q * 128 + lane * 4;
        int4 dd = *(const int4*)(dbat + i);
        const int full = dd.x + dd.y + dd.z + dd.w;
        packed += full + (((i < l0) ? full : 0) << 16);
    }
    #pragma unroll
    for (int o = 16; o > 0; o >>= 1)
        packed += __shfl_xor_sync(0xffffffffu, packed, o);

    const int total  = packed & 0xFFFF;
    const int prefix = packed >> 16;

    // ---- 16 block durations (warp-uniform L1-hit int4 loads);
    //      capture start/d for my 4 phonemes p = fgrp + 4i on the fly.
    const int4 q0 = *(const int4*)(dbat + l0);
    const int4 q1 = *(const int4*)(dbat + l0 + 4);
    const int4 q2 = *(const int4*)(dbat + l0 + 8);
    const int4 q3 = *(const int4*)(dbat + l0 + 12);
    const int du[16] = { q0.x,q0.y,q0.z,q0.w, q1.x,q1.y,q1.z,q1.w,
                         q2.x,q2.y,q2.z,q2.w, q3.x,q3.y,q3.z,q3.w };
    int st[4], dd[4];
    int run = prefix;
    #pragma unroll
    for (int k = 0; k < 16; ++k) {
        if ((k & 3) == fgrp) { st[k >> 2] = run; dd[k >> 2] = du[k]; }
        run += du[k];
    }

    // ---- replicate 4 phoneme rows; prefetch next row during current stores.
    const float4* __restrict__ src =
        hidden4 + ((size_t)b * L_CONST + l0) * D4 + lane64;
    float4* __restrict__ obase = out4 + (size_t)b * max_T * D4 + lane64;

    float4 v = src[fgrp * D4];
    #pragma unroll
    for (int i = 0; i < 4; ++i) {
        float4 vn;
        if (i < 3) vn = src[(fgrp + 4 * (i + 1)) * D4];
        float4* dst = obase + (size_t)st[i] * D4;
        const int d = dd[i];                     // warp-uniform
        for (int j = 0; j < d; ++j)              // exact trip
            dst[j * D4] = v;
        v = vn;
    }

    // ---- tail zeroing: strided share of [total, max_T), 128 frames/step
    const float4 zero = make_float4(0.f, 0.f, 0.f, 0.f);
    for (int f = total + blkLocal * 4 + fgrp; f < max_T; f += 4 * BLOCKS_PER_BATCH) {
        obase[(size_t)f * D4] = zero;
    }
}

extern "C" void kernel_launch(void* const* d_in, const int* in_sizes, int n_in,
                              void* d_out, int out_size) {
    const float* hidden    = (const float*)d_in[0];   // [B, L, D] fp32
    const int*   durations = (const int*)d_in[1];     // [B, L] int32
    float*       out       = (float*)d_out;

    const int max_T = out_size / (B_CONST * D_CONST);

    lr_fused<<<B_CONST * BLOCKS_PER_BATCH, 256>>>(
        (const float4*)hidden, durations, (float4*)out, max_T);
}